// round 1
// baseline (speedup 1.0000x reference)
#include <cuda_runtime.h>
#include <math.h>

// Problem constants
#define N_ROWS   4096
#define D_DIM    1024
#define TEMP_INV 20.0f      // 1 / 0.05
#define HARD_NEG_W 1.0f
#define EPS_N    1e-8f

// GEMM tiling
#define BM 64
#define BN 64
#define BK 16
#define NCT 128             // column tiles: 2N / BN

// Scratch (device globals — no allocation allowed)
__device__ float g_inv[3][N_ROWS];              // inverse row norms: x, t, h
__device__ float g_partial[(size_t)N_ROWS * NCT]; // per (row, col-tile) sum of exp
__device__ float g_diag[N_ROWS];                // pos_sim[i,i] * TEMP_INV

// ---------------------------------------------------------------------------
// Kernel 1: inverse row norms. One warp per row, 3*4096 rows.
// ---------------------------------------------------------------------------
__global__ void __launch_bounds__(256) norm_kernel(const float* __restrict__ x,
                                                   const float* __restrict__ t,
                                                   const float* __restrict__ h) {
    int warp = (blockIdx.x * blockDim.x + threadIdx.x) >> 5;
    int lane = threadIdx.x & 31;
    if (warp >= 3 * N_ROWS) return;
    int mat = warp / N_ROWS;
    int row = warp - mat * N_ROWS;
    const float* src = (mat == 0) ? x : (mat == 1 ? t : h);
    const float4* p = (const float4*)(src + (size_t)row * D_DIM);
    float s = 0.f;
#pragma unroll
    for (int i = 0; i < D_DIM / 4 / 32; i++) {
        float4 v = p[lane + i * 32];
        s += v.x * v.x + v.y * v.y + v.z * v.z + v.w * v.w;
    }
#pragma unroll
    for (int o = 16; o; o >>= 1) s += __shfl_xor_sync(0xffffffffu, s, o);
    if (lane == 0) {
        float n = fmaxf(sqrtf(s), EPS_N);
        g_inv[mat][row] = 1.0f / n;
    }
}

// ---------------------------------------------------------------------------
// Kernel 2: fused similarity GEMM + exp + per-tile row sums.
// Grid: (NCT=128 col tiles, 64 row tiles). Block: 256 threads, 4x4 microtile.
// ---------------------------------------------------------------------------
__global__ void __launch_bounds__(256) sim_kernel(const float* __restrict__ x,
                                                  const float* __restrict__ t,
                                                  const float* __restrict__ h) {
    __shared__ float As[BK][BM];
    __shared__ float Bs[BK][BN];
    __shared__ float sred[BM][16];

    const int ct  = blockIdx.x;          // 0..127  (col tile over [T; H])
    const int rt  = blockIdx.y;          // 0..63   (row tile over X)
    const int tid = threadIdx.x;
    const int tx  = tid & 15;            // 0..15
    const int ty  = tid >> 4;            // 0..15

    const bool isNeg = (ct >= 64);
    const float* Bmat = isNeg ? h : t;
    const int cbase = (ct & 63) * BN;
    const int rbase = rt * BM;

    // cooperative tile-load indices: each thread loads one float4 of A and B
    const int lrow = tid >> 2;           // 0..63
    const int lk   = (tid & 3) * 4;      // 0,4,8,12

    const float* Aptr = x    + (size_t)(rbase + lrow) * D_DIM + lk;
    const float* Bptr = Bmat + (size_t)(cbase + lrow) * D_DIM + lk;

    float acc[4][4];
#pragma unroll
    for (int i = 0; i < 4; i++)
#pragma unroll
        for (int j = 0; j < 4; j++) acc[i][j] = 0.f;

    for (int k0 = 0; k0 < D_DIM; k0 += BK) {
        float4 av = *(const float4*)(Aptr + k0);
        float4 bv = *(const float4*)(Bptr + k0);
        As[lk + 0][lrow] = av.x;
        As[lk + 1][lrow] = av.y;
        As[lk + 2][lrow] = av.z;
        As[lk + 3][lrow] = av.w;
        Bs[lk + 0][lrow] = bv.x;
        Bs[lk + 1][lrow] = bv.y;
        Bs[lk + 2][lrow] = bv.z;
        Bs[lk + 3][lrow] = bv.w;
        __syncthreads();
#pragma unroll
        for (int k = 0; k < BK; k++) {
            float a[4], b[4];
            *(float4*)a = *(const float4*)&As[k][ty * 4];
            *(float4*)b = *(const float4*)&Bs[k][tx * 4];
#pragma unroll
            for (int i = 0; i < 4; i++)
#pragma unroll
                for (int j = 0; j < 4; j++) acc[i][j] = fmaf(a[i], b[j], acc[i][j]);
        }
        __syncthreads();
    }

    // Epilogue: scale, weight, exp, per-row partial sums. Deterministic writes.
    float invA[4], invB[4];
#pragma unroll
    for (int i = 0; i < 4; i++) invA[i] = g_inv[0][rbase + ty * 4 + i] * TEMP_INV;
    const int matB = isNeg ? 2 : 1;
#pragma unroll
    for (int j = 0; j < 4; j++) invB[j] = g_inv[matB][cbase + tx * 4 + j];

    float rowsum[4] = {0.f, 0.f, 0.f, 0.f};
#pragma unroll
    for (int i = 0; i < 4; i++) {
        const int gi = rbase + ty * 4 + i;
#pragma unroll
        for (int j = 0; j < 4; j++) {
            const int gj = cbase + tx * 4 + j;
            float s = acc[i][j] * invA[i] * invB[j];
            if (gi == gj) {
                if (isNeg) s += HARD_NEG_W;   // hard-negative boost on neg diagonal
                else       g_diag[gi] = s;    // positive-pair logit (single writer)
            }
            rowsum[i] += __expf(s);
        }
    }
#pragma unroll
    for (int i = 0; i < 4; i++) sred[ty * 4 + i][tx] = rowsum[i];
    __syncthreads();
    if (tid < BM) {
        float s = 0.f;
#pragma unroll
        for (int q = 0; q < 16; q++) s += sred[tid][q];
        g_partial[(size_t)(rbase + tid) * NCT + ct] = s;
    }
}

// ---------------------------------------------------------------------------
// Kernel 3: finalize. loss = mean_i( log(sum_exp_i) - pos_diag_i )
// ---------------------------------------------------------------------------
__global__ void __launch_bounds__(256) finalize_kernel(float* __restrict__ out) {
    __shared__ float sm[256];
    const int tid = threadIdx.x;
    float local = 0.f;
    for (int row = tid; row < N_ROWS; row += 256) {
        const float* p = &g_partial[(size_t)row * NCT];
        float s = 0.f;
#pragma unroll 8
        for (int c = 0; c < NCT; c++) s += p[c];
        local += logf(s) - g_diag[row];
    }
    sm[tid] = local;
    __syncthreads();
#pragma unroll
    for (int o = 128; o; o >>= 1) {
        if (tid < o) sm[tid] += sm[tid + o];
        __syncthreads();
    }
    if (tid == 0) out[0] = sm[0] * (1.0f / N_ROWS);
}

// ---------------------------------------------------------------------------
extern "C" void kernel_launch(void* const* d_in, const int* in_sizes, int n_in,
                              void* d_out, int out_size) {
    const float* x = (const float*)d_in[0];   // input
    const float* t = (const float*)d_in[1];   // target
    const float* h = (const float*)d_in[2];   // hard_negative
    float* out = (float*)d_out;

    // 3*4096 warps, 8 warps per block
    norm_kernel<<<(3 * N_ROWS) / 8, 256>>>(x, t, h);

    dim3 grid(NCT, N_ROWS / BM);
    sim_kernel<<<grid, 256>>>(x, t, h);

    finalize_kernel<<<1, 256>>>(out);
}

// round 3
// speedup vs baseline: 6.4724x; 6.4724x over previous
#include <cuda_runtime.h>
#include <cuda_bf16.h>
#include <math.h>
#include <stdint.h>

#define N_ROWS   4096
#define D_DIM    1024
#define TEMP_INV 20.0f
#define EPS_N    1e-8f

// GEMM tiling
#define BM 128
#define BN 128
#define BK 32
#define NKC (D_DIM / BK)          // 32 K-chunks
#define CT_N (2 * N_ROWS / BN)    // 64 col tiles
#define RT_N (N_ROWS / BM)        // 32 row tiles
#define ROWB 80                   // padded smem row stride in bytes (32 bf16 = 64B + 16B pad)

// Scratch (device globals — no allocation allowed)
__device__ __nv_bfloat16 g_b[3][(size_t)N_ROWS * D_DIM];   // normalized bf16 (x scaled by 20)
__device__ float g_partial[(size_t)N_ROWS * CT_N];
__device__ float g_diag[N_ROWS];

// ---------------------------------------------------------------------------
__device__ __forceinline__ uint32_t smem_u32(const void* p) {
    uint32_t a;
    asm("{ .reg .u64 t; cvta.to.shared.u64 t, %1; cvt.u32.u64 %0, t; }"
        : "=r"(a) : "l"(p));
    return a;
}

#define LDSM_X4(r, addr) \
    asm volatile("ldmatrix.sync.aligned.m8n8.x4.shared.b16 {%0,%1,%2,%3}, [%4];" \
                 : "=r"((r)[0]), "=r"((r)[1]), "=r"((r)[2]), "=r"((r)[3]) : "r"(addr))

#define MMA16816(d, a, b) \
    asm volatile("mma.sync.aligned.m16n8k16.row.col.f32.bf16.bf16.f32 " \
                 "{%0,%1,%2,%3}, {%4,%5,%6,%7}, {%8,%9}, {%0,%1,%2,%3};" \
                 : "+f"((d)[0]), "+f"((d)[1]), "+f"((d)[2]), "+f"((d)[3]) \
                 : "r"((a)[0]), "r"((a)[1]), "r"((a)[2]), "r"((a)[3]), \
                   "r"((b)[0]), "r"((b)[1]))

#define CP_ASYNC16(so, gp) \
    asm volatile("cp.async.cg.shared.global [%0], [%1], 16;" \
                 :: "r"(so), "l"(__cvta_generic_to_global(gp)))
#define CP_COMMIT()  asm volatile("cp.async.commit_group;" ::: "memory")
#define CP_WAIT(n)   asm volatile("cp.async.wait_group %0;" :: "n"(n) : "memory")

// ---------------------------------------------------------------------------
// Kernel 1: row norms + normalize (+ fold 1/TEMP into x) + bf16 convert.
// One warp per row; 3*4096 warps.
// ---------------------------------------------------------------------------
__global__ void __launch_bounds__(256) norm_convert_kernel(const float* __restrict__ x,
                                                           const float* __restrict__ t,
                                                           const float* __restrict__ h) {
    int warp = (blockIdx.x * blockDim.x + threadIdx.x) >> 5;
    int lane = threadIdx.x & 31;
    if (warp >= 3 * N_ROWS) return;
    int mat = warp / N_ROWS;
    int row = warp - mat * N_ROWS;
    const float* src = (mat == 0) ? x : (mat == 1 ? t : h);
    const float4* p = (const float4*)(src + (size_t)row * D_DIM);
    float4 v[8];
    float s = 0.f;
#pragma unroll
    for (int i = 0; i < 8; i++) {
        v[i] = p[lane + i * 32];
        s += v[i].x * v[i].x + v[i].y * v[i].y + v[i].z * v[i].z + v[i].w * v[i].w;
    }
#pragma unroll
    for (int o = 16; o; o >>= 1) s += __shfl_xor_sync(0xffffffffu, s, o);
    float inv = 1.0f / fmaxf(sqrtf(s), EPS_N);
    float sc = (mat == 0) ? inv * TEMP_INV : inv;
    uint2* dst = (uint2*)(&g_b[mat][(size_t)row * D_DIM]);
#pragma unroll
    for (int i = 0; i < 8; i++) {
        __nv_bfloat162 p0 = __floats2bfloat162_rn(v[i].x * sc, v[i].y * sc);
        __nv_bfloat162 p1 = __floats2bfloat162_rn(v[i].z * sc, v[i].w * sc);
        uint2 u;
        u.x = *(uint32_t*)&p0;
        u.y = *(uint32_t*)&p1;
        dst[lane + i * 32] = u;
    }
}

// ---------------------------------------------------------------------------
// Kernel 2: bf16 mma.sync GEMM 128x128 tile, K=1024, fused exp epilogue.
// 8 warps: 2 (M) x 4 (N); warp tile 64x32; double-buffered cp.async.
// ---------------------------------------------------------------------------
__global__ void __launch_bounds__(256) sim_mma_kernel() {
    __shared__ __align__(16) char sA[2][BM * ROWB];
    __shared__ __align__(16) char sB[2][BN * ROWB];
    __shared__ float sred[BM][4];

    const int tid = threadIdx.x;
    const int lane = tid & 31;
    const int wid = tid >> 5;
    const int wm = wid & 1;           // 0..1 (64 rows each)
    const int wn = wid >> 1;          // 0..3 (32 cols each)

    const int ct = blockIdx.x;        // 0..63
    const int rt = blockIdx.y;        // 0..31
    const int rbase = rt * BM;
    const int cbase = ct * BN;        // global col in [0, 8192)
    const bool isNeg = (cbase >= N_ROWS);
    const __nv_bfloat16* Bmat = isNeg ? g_b[2] : g_b[1];
    const int cloc = isNeg ? (cbase - N_ROWS) : cbase;

    const char* Ag = (const char*)(g_b[0] + (size_t)rbase * D_DIM);
    const char* Bg = (const char*)(Bmat + (size_t)cloc * D_DIM);

    // per-thread load slots: 2 x 16B pieces of A and of B per chunk
    int p0 = tid, p1 = tid + 256;
    int r0 = p0 >> 2, c0 = p0 & 3;
    int r1 = p1 >> 2, c1 = p1 & 3;
    uint32_t soA0[2], soA1[2], soB0[2], soB1[2];
#pragma unroll
    for (int b = 0; b < 2; b++) {
        soA0[b] = smem_u32(&sA[b][r0 * ROWB + c0 * 16]);
        soA1[b] = smem_u32(&sA[b][r1 * ROWB + c1 * 16]);
        soB0[b] = smem_u32(&sB[b][r0 * ROWB + c0 * 16]);
        soB1[b] = smem_u32(&sB[b][r1 * ROWB + c1 * 16]);
    }

#define LOAD_CHUNK(c, b)                                                  \
    do {                                                                  \
        const char* ga0 = Ag + (size_t)r0 * 2048 + (c) * 64 + c0 * 16;    \
        const char* ga1 = Ag + (size_t)r1 * 2048 + (c) * 64 + c1 * 16;    \
        const char* gb0 = Bg + (size_t)r0 * 2048 + (c) * 64 + c0 * 16;    \
        const char* gb1 = Bg + (size_t)r1 * 2048 + (c) * 64 + c1 * 16;    \
        CP_ASYNC16(soA0[b], ga0);                                         \
        CP_ASYNC16(soA1[b], ga1);                                         \
        CP_ASYNC16(soB0[b], gb0);                                         \
        CP_ASYNC16(soB1[b], gb1);                                         \
        CP_COMMIT();                                                      \
    } while (0)

    float acc[4][4][4];
#pragma unroll
    for (int i = 0; i < 4; i++)
#pragma unroll
        for (int j = 0; j < 4; j++)
#pragma unroll
            for (int q = 0; q < 4; q++) acc[i][j][q] = 0.f;

    LOAD_CHUNK(0, 0);

    // precomputed ldmatrix smem offsets (within a buffer)
    const int aRowSel = (lane & 15);
    const int aChkSel = (lane >> 4);          // 0/1
    const int bRowSel = ((lane >> 4) ? 8 : 0) + (lane & 7);
    const int bChkSel = ((lane >> 3) & 1);

    for (int c = 0; c < NKC; c++) {
        const int buf = c & 1;
        if (c + 1 < NKC) {
            LOAD_CHUNK(c + 1, buf ^ 1);
            CP_WAIT(1);
        } else {
            CP_WAIT(0);
        }
        __syncthreads();

        const uint32_t aBase = smem_u32(&sA[buf][0]);
        const uint32_t bBase = smem_u32(&sB[buf][0]);
#pragma unroll
        for (int ks = 0; ks < 2; ks++) {
            uint32_t afr[4][4], bfr[4][2];
#pragma unroll
            for (int mt = 0; mt < 4; mt++) {
                int row = wm * 64 + mt * 16 + aRowSel;
                int chk = ks * 2 + aChkSel;
                LDSM_X4(afr[mt], aBase + row * ROWB + chk * 16);
            }
#pragma unroll
            for (int np = 0; np < 2; np++) {
                int nrow = wn * 32 + np * 16 + bRowSel;
                int chk = ks * 2 + bChkSel;
                uint32_t r[4];
                LDSM_X4(r, bBase + nrow * ROWB + chk * 16);
                bfr[np * 2 + 0][0] = r[0];
                bfr[np * 2 + 0][1] = r[1];
                bfr[np * 2 + 1][0] = r[2];
                bfr[np * 2 + 1][1] = r[3];
            }
#pragma unroll
            for (int mt = 0; mt < 4; mt++)
#pragma unroll
                for (int nt = 0; nt < 4; nt++) MMA16816(acc[mt][nt], afr[mt], bfr[nt]);
        }
        __syncthreads();
    }

    // Epilogue: diag fixup, exp, per-row sums. C frag: lane g=l>>2, t2=(l&3)*2;
    // regs: 0:(r+g, c+t2) 1:(r+g, c+t2+1) 2:(r+g+8, c+t2) 3:(r+g+8, c+t2+1)
    const int g = lane >> 2;
    const int t2 = (lane & 3) * 2;
    const int diagOff = isNeg ? N_ROWS : 0;

#pragma unroll
    for (int mt = 0; mt < 4; mt++) {
        const int gi0 = rbase + wm * 64 + mt * 16 + g;
        const int gi1 = gi0 + 8;
        const int d0 = gi0 + diagOff;
        const int d1 = gi1 + diagOff;
        float s0 = 0.f, s1 = 0.f;
#pragma unroll
        for (int nt = 0; nt < 4; nt++) {
            const int gc = cbase + wn * 32 + nt * 8 + t2;
            float v0 = acc[mt][nt][0];
            float v1 = acc[mt][nt][1];
            float v2 = acc[mt][nt][2];
            float v3 = acc[mt][nt][3];
            if (gc == d0)     { if (isNeg) v0 += 1.f; else g_diag[gi0] = v0; }
            if (gc + 1 == d0) { if (isNeg) v1 += 1.f; else g_diag[gi0] = v1; }
            if (gc == d1)     { if (isNeg) v2 += 1.f; else g_diag[gi1] = v2; }
            if (gc + 1 == d1) { if (isNeg) v3 += 1.f; else g_diag[gi1] = v3; }
            s0 += __expf(v0) + __expf(v1);
            s1 += __expf(v2) + __expf(v3);
        }
        // quad reduce across lanes sharing the same row
        s0 += __shfl_xor_sync(0xffffffffu, s0, 1);
        s0 += __shfl_xor_sync(0xffffffffu, s0, 2);
        s1 += __shfl_xor_sync(0xffffffffu, s1, 1);
        s1 += __shfl_xor_sync(0xffffffffu, s1, 2);
        if ((lane & 3) == 0) {
            sred[wm * 64 + mt * 16 + g][wn] = s0;
            sred[wm * 64 + mt * 16 + g + 8][wn] = s1;
        }
    }
    __syncthreads();
    if (tid < BM) {
        float s = sred[tid][0] + sred[tid][1] + sred[tid][2] + sred[tid][3];
        g_partial[(size_t)(rbase + tid) * CT_N + ct] = s;
    }
}

// ---------------------------------------------------------------------------
// Kernel 3: finalize. loss = mean_i( log(sum_exp_i) - pos_diag_i )
// ---------------------------------------------------------------------------
__global__ void __launch_bounds__(256) finalize_kernel(float* __restrict__ out) {
    __shared__ float sm[256];
    const int tid = threadIdx.x;
    float local = 0.f;
    for (int row = tid; row < N_ROWS; row += 256) {
        const float* p = &g_partial[(size_t)row * CT_N];
        float s = 0.f;
#pragma unroll
        for (int c = 0; c < CT_N; c++) s += p[c];
        local += logf(s) - g_diag[row];
    }
    sm[tid] = local;
    __syncthreads();
#pragma unroll
    for (int o = 128; o; o >>= 1) {
        if (tid < o) sm[tid] += sm[tid + o];
        __syncthreads();
    }
    if (tid == 0) out[0] = sm[0] * (1.0f / N_ROWS);
}

// ---------------------------------------------------------------------------
extern "C" void kernel_launch(void* const* d_in, const int* in_sizes, int n_in,
                              void* d_out, int out_size) {
    const float* x = (const float*)d_in[0];
    const float* t = (const float*)d_in[1];
    const float* h = (const float*)d_in[2];
    float* out = (float*)d_out;

    norm_convert_kernel<<<(3 * N_ROWS) / 8, 256>>>(x, t, h);

    dim3 grid(CT_N, RT_N);
    sim_mma_kernel<<<grid, 256>>>();

    finalize_kernel<<<1, 256>>>(out);
}

// round 4
// speedup vs baseline: 7.2689x; 1.1231x over previous
#include <cuda_runtime.h>
#include <cuda_bf16.h>
#include <math.h>
#include <stdint.h>

#define N_ROWS   4096
#define D_DIM    1024
#define TEMP_INV 20.0f
#define EPS_N    1e-8f
#define QSCALE   16.0f        // fp8 quantization scale (both operands)
#define ISC2     (1.0f / (QSCALE * QSCALE))

// GEMM tiling (fp8 e4m3, K measured in bytes == elements)
#define BM 128
#define BN 256
#define BK 64                 // K bytes per smem chunk
#define NKC (D_DIM / BK)      // 16 chunks
#define CT_N (2 * N_ROWS / BN)  // 32 col tiles
#define RT_N (N_ROWS / BM)      // 32 row tiles
#define ROWB 80               // padded smem row stride (64 B data + 16 B pad)

// dynamic smem layout
#define SM_A0   0
#define SM_A1   (BM * ROWB)               // 10240
#define SM_B0   (2 * BM * ROWB)           // 20480
#define SM_B1   (2 * BM * ROWB + BN * ROWB)   // 40960
#define SM_SRED (2 * BM * ROWB + 2 * BN * ROWB) // 61440
#define SMEM_TOTAL (SM_SRED + BM * 4 * 4)     // 63488

// Scratch
__device__ uint8_t g_q[3][(size_t)N_ROWS * D_DIM];   // e4m3, normalized & scaled
__device__ float g_partial[(size_t)N_ROWS * CT_N];
__device__ float g_diag[N_ROWS];

// ---------------------------------------------------------------------------
__device__ __forceinline__ uint32_t smem_u32(const void* p) {
    uint32_t a;
    asm("{ .reg .u64 t; cvta.to.shared.u64 t, %1; cvt.u32.u64 %0, t; }"
        : "=r"(a) : "l"(p));
    return a;
}

#define LDSM_X4(r, addr) \
    asm volatile("ldmatrix.sync.aligned.m8n8.x4.shared.b16 {%0,%1,%2,%3}, [%4];" \
                 : "=r"((r)[0]), "=r"((r)[1]), "=r"((r)[2]), "=r"((r)[3]) : "r"(addr))

#define MMA_FP8(d, a, b) \
    asm volatile("mma.sync.aligned.m16n8k32.row.col.f32.e4m3.e4m3.f32 " \
                 "{%0,%1,%2,%3}, {%4,%5,%6,%7}, {%8,%9}, {%0,%1,%2,%3};" \
                 : "+f"((d)[0]), "+f"((d)[1]), "+f"((d)[2]), "+f"((d)[3]) \
                 : "r"((a)[0]), "r"((a)[1]), "r"((a)[2]), "r"((a)[3]), \
                   "r"((b)[0]), "r"((b)[1]))

#define CP_ASYNC16(so, gp) \
    asm volatile("cp.async.cg.shared.global [%0], [%1], 16;" \
                 :: "r"(so), "l"(__cvta_generic_to_global(gp)))
#define CP_COMMIT()  asm volatile("cp.async.commit_group;" ::: "memory")
#define CP_WAIT(n)   asm volatile("cp.async.wait_group %0;" :: "n"(n) : "memory")

__device__ __forceinline__ uint32_t pack4_e4m3(float4 v) {
    uint16_t lo, hi;
    // cvt d, a, b: byte1 = cvt(a), byte0 = cvt(b)
    asm("cvt.rn.satfinite.e4m3x2.f32 %0, %1, %2;" : "=h"(lo) : "f"(v.y), "f"(v.x));
    asm("cvt.rn.satfinite.e4m3x2.f32 %0, %1, %2;" : "=h"(hi) : "f"(v.w), "f"(v.z));
    return (uint32_t)lo | ((uint32_t)hi << 16);
}

// ---------------------------------------------------------------------------
// Kernel 1: row norms + normalize (+ fold 1/TEMP into x) + scale + e4m3.
// One warp per row; 3*4096 warps.
// ---------------------------------------------------------------------------
__global__ void __launch_bounds__(256) norm_convert_kernel(const float* __restrict__ x,
                                                           const float* __restrict__ t,
                                                           const float* __restrict__ h) {
    int warp = (blockIdx.x * blockDim.x + threadIdx.x) >> 5;
    int lane = threadIdx.x & 31;
    if (warp >= 3 * N_ROWS) return;
    int mat = warp / N_ROWS;
    int row = warp - mat * N_ROWS;
    const float* src = (mat == 0) ? x : (mat == 1 ? t : h);
    const float4* p = (const float4*)(src + (size_t)row * D_DIM);
    float4 v[8];
    float s = 0.f;
#pragma unroll
    for (int i = 0; i < 8; i++) {
        v[i] = p[lane + i * 32];
        s += v[i].x * v[i].x + v[i].y * v[i].y + v[i].z * v[i].z + v[i].w * v[i].w;
    }
#pragma unroll
    for (int o = 16; o; o >>= 1) s += __shfl_xor_sync(0xffffffffu, s, o);
    float inv = 1.0f / fmaxf(sqrtf(s), EPS_N);
    float sc = ((mat == 0) ? inv * TEMP_INV : inv) * QSCALE;
    uint32_t* dst = (uint32_t*)(&g_q[mat][(size_t)row * D_DIM]);
#pragma unroll
    for (int i = 0; i < 8; i++) {
        float4 w;
        w.x = v[i].x * sc; w.y = v[i].y * sc; w.z = v[i].z * sc; w.w = v[i].w * sc;
        dst[lane + i * 32] = pack4_e4m3(w);
    }
}

// ---------------------------------------------------------------------------
// Kernel 2: e4m3 mma.sync GEMM, CTA tile 128x256, warp tile 64x64, K=1024.
// 8 warps (2 M x 4 N), double-buffered cp.async, fused exp epilogue.
// ---------------------------------------------------------------------------
__global__ void __launch_bounds__(256) sim_fp8_kernel() {
    extern __shared__ __align__(16) char dsm[];
    const int tid = threadIdx.x;
    const int lane = tid & 31;
    const int wid = tid >> 5;
    const int wm = wid & 1;           // row half (64 rows)
    const int wn = wid >> 1;          // col quarter (64 cols)

    const int ct = blockIdx.x;        // 0..31
    const int rt = blockIdx.y;        // 0..31
    const int rbase = rt * BM;
    const int cbase = ct * BN;
    const bool isNeg = (cbase >= N_ROWS);
    const uint8_t* Bmat = isNeg ? g_q[2] : g_q[1];
    const int cloc = isNeg ? (cbase - N_ROWS) : cbase;

    const uint8_t* Ag = g_q[0] + (size_t)rbase * D_DIM;
    const uint8_t* Bg = Bmat + (size_t)cloc * D_DIM;

    // cp.async slots: A = 128 rows x 4 segs(16B) = 512 (2/thread);
    //                 B = 256 rows x 4 segs     = 1024 (4/thread)
    const int ar0 = tid >> 1;                  // wrong granularity? use slot math:
    (void)ar0;
    uint32_t sA[2], sAoff[2], sB[4], sBoff[4];
#pragma unroll
    for (int q = 0; q < 2; q++) {
        int slot = tid + q * 256;
        int r = slot >> 2, sgm = slot & 3;
        sA[q] = (uint32_t)(r * ROWB + sgm * 16);
        sAoff[q] = (uint32_t)(r * D_DIM + sgm * 16);
    }
#pragma unroll
    for (int q = 0; q < 4; q++) {
        int slot = tid + q * 256;
        int r = slot >> 2, sgm = slot & 3;
        sB[q] = (uint32_t)(r * ROWB + sgm * 16);
        sBoff[q] = (uint32_t)(r * D_DIM + sgm * 16);
    }
    const uint32_t smA[2] = { smem_u32(dsm + SM_A0), smem_u32(dsm + SM_A1) };
    const uint32_t smB[2] = { smem_u32(dsm + SM_B0), smem_u32(dsm + SM_B1) };

#define LOAD_CHUNK(c, b)                                            \
    do {                                                            \
        const uint32_t k0 = (c) * BK;                               \
        CP_ASYNC16(smA[b] + sA[0], Ag + sAoff[0] + k0);             \
        CP_ASYNC16(smA[b] + sA[1], Ag + sAoff[1] + k0);             \
        CP_ASYNC16(smB[b] + sB[0], Bg + sBoff[0] + k0);             \
        CP_ASYNC16(smB[b] + sB[1], Bg + sBoff[1] + k0);             \
        CP_ASYNC16(smB[b] + sB[2], Bg + sBoff[2] + k0);             \
        CP_ASYNC16(smB[b] + sB[3], Bg + sBoff[3] + k0);             \
        CP_COMMIT();                                                \
    } while (0)

    float acc[4][8][4];
#pragma unroll
    for (int i = 0; i < 4; i++)
#pragma unroll
        for (int j = 0; j < 8; j++)
#pragma unroll
            for (int q = 0; q < 4; q++) acc[i][j][q] = 0.f;

    LOAD_CHUNK(0, 0);

    // ldmatrix lane addressing (byte-identical to verified bf16 round-3 scheme)
    const int aRow = lane & 15;            // rows 0..15 of a 16-row tile
    const int aSeg = (lane >> 4) * 16;     // byte 0 or 16 within 32B k-slice
    const int bRow = ((lane >> 4) ? 8 : 0) + (lane & 7);
    const int bSeg = ((lane >> 3) & 1) * 16;

    for (int c = 0; c < NKC; c++) {
        const int buf = c & 1;
        if (c + 1 < NKC) {
            LOAD_CHUNK(c + 1, buf ^ 1);
            CP_WAIT(1);
        } else {
            CP_WAIT(0);
        }
        __syncthreads();

        const uint32_t aB = smA[buf];
        const uint32_t bB = smB[buf];
#pragma unroll
        for (int ks = 0; ks < 2; ks++) {       // two 32B k-slices per chunk
            const int kso = ks * 32;
            uint32_t afr[4][4], bfr[8][2];
#pragma unroll
            for (int mt = 0; mt < 4; mt++) {
                int row = wm * 64 + mt * 16 + aRow;
                LDSM_X4(afr[mt], aB + row * ROWB + kso + aSeg);
            }
#pragma unroll
            for (int np = 0; np < 4; np++) {   // each LDSM covers 16 n-rows
                int nrow = wn * 64 + np * 16 + bRow;
                uint32_t r[4];
                LDSM_X4(r, bB + nrow * ROWB + kso + bSeg);
                bfr[np * 2 + 0][0] = r[0];
                bfr[np * 2 + 0][1] = r[1];
                bfr[np * 2 + 1][0] = r[2];
                bfr[np * 2 + 1][1] = r[3];
            }
#pragma unroll
            for (int mt = 0; mt < 4; mt++)
#pragma unroll
                for (int nt = 0; nt < 8; nt++) MMA_FP8(acc[mt][nt], afr[mt], bfr[nt]);
        }
        __syncthreads();
    }

    // Epilogue: rescale, diag fixup, exp, per-row sums.
    const int g = lane >> 2;
    const int t2 = (lane & 3) * 2;
    const int diagOff = isNeg ? N_ROWS : 0;
    float* sred = (float*)(dsm + SM_SRED);

#pragma unroll
    for (int mt = 0; mt < 4; mt++) {
        const int gi0 = rbase + wm * 64 + mt * 16 + g;
        const int gi1 = gi0 + 8;
        const int d0 = gi0 + diagOff;
        const int d1 = gi1 + diagOff;
        float s0 = 0.f, s1 = 0.f;
#pragma unroll
        for (int nt = 0; nt < 8; nt++) {
            const int gc = cbase + wn * 64 + nt * 8 + t2;
            float v0 = acc[mt][nt][0] * ISC2;
            float v1 = acc[mt][nt][1] * ISC2;
            float v2 = acc[mt][nt][2] * ISC2;
            float v3 = acc[mt][nt][3] * ISC2;
            if (gc == d0)     { if (isNeg) v0 += 1.f; else g_diag[gi0] = v0; }
            if (gc + 1 == d0) { if (isNeg) v1 += 1.f; else g_diag[gi0] = v1; }
            if (gc == d1)     { if (isNeg) v2 += 1.f; else g_diag[gi1] = v2; }
            if (gc + 1 == d1) { if (isNeg) v3 += 1.f; else g_diag[gi1] = v3; }
            s0 += __expf(v0) + __expf(v1);
            s1 += __expf(v2) + __expf(v3);
        }
        s0 += __shfl_xor_sync(0xffffffffu, s0, 1);
        s0 += __shfl_xor_sync(0xffffffffu, s0, 2);
        s1 += __shfl_xor_sync(0xffffffffu, s1, 1);
        s1 += __shfl_xor_sync(0xffffffffu, s1, 2);
        if ((lane & 3) == 0) {
            sred[(wm * 64 + mt * 16 + g) * 4 + wn] = s0;
            sred[(wm * 64 + mt * 16 + g + 8) * 4 + wn] = s1;
        }
    }
    __syncthreads();
    if (tid < BM) {
        float s = sred[tid * 4] + sred[tid * 4 + 1] + sred[tid * 4 + 2] + sred[tid * 4 + 3];
        g_partial[(size_t)(rbase + tid) * CT_N + ct] = s;
    }
}

// ---------------------------------------------------------------------------
// Kernel 3: finalize. loss = mean_i( log(sum_exp_i) - pos_diag_i )
// ---------------------------------------------------------------------------
__global__ void __launch_bounds__(256) finalize_kernel(float* __restrict__ out) {
    __shared__ float sm[256];
    const int tid = threadIdx.x;
    float local = 0.f;
    for (int row = tid; row < N_ROWS; row += 256) {
        const float* p = &g_partial[(size_t)row * CT_N];
        float s = 0.f;
#pragma unroll
        for (int c = 0; c < CT_N; c++) s += p[c];
        local += logf(s) - g_diag[row];
    }
    sm[tid] = local;
    __syncthreads();
#pragma unroll
    for (int o = 128; o; o >>= 1) {
        if (tid < o) sm[tid] += sm[tid + o];
        __syncthreads();
    }
    if (tid == 0) out[0] = sm[0] * (1.0f / N_ROWS);
}

// ---------------------------------------------------------------------------
extern "C" void kernel_launch(void* const* d_in, const int* in_sizes, int n_in,
                              void* d_out, int out_size) {
    const float* x = (const float*)d_in[0];
    const float* t = (const float*)d_in[1];
    const float* h = (const float*)d_in[2];
    float* out = (float*)d_out;

    cudaFuncSetAttribute(sim_fp8_kernel,
                         cudaFuncAttributeMaxDynamicSharedMemorySize, SMEM_TOTAL);

    norm_convert_kernel<<<(3 * N_ROWS) / 8, 256>>>(x, t, h);

    dim3 grid(CT_N, RT_N);
    sim_fp8_kernel<<<grid, 256, SMEM_TOTAL>>>();

    finalize_kernel<<<1, 256>>>(out);
}

// round 5
// speedup vs baseline: 9.9365x; 1.3670x over previous
#include <cuda_runtime.h>
#include <cuda_bf16.h>
#include <math.h>
#include <stdint.h>

#define N_ROWS   4096
#define D_DIM    1024
#define TEMP_INV 20.0f
#define EPS_N    1e-8f
#define QSCALE   16.0f
#define ISC2     (1.0f / (QSCALE * QSCALE))

// GEMM tiling (fp8 e4m3; K in bytes == elements)
#define BM 128
#define BN 256
#define BK 64
#define NKC (D_DIM / BK)         // 16 chunks
#define NSTAGE 4
#define CT_N (2 * N_ROWS / BN)   // 32 col tiles
#define RT_N (N_ROWS / BM)       // 32 row tiles
#define ROWB 80                  // padded smem row stride (64B data + 16B pad)
#define NTHREADS 512

// dynamic smem layout: 4 stages of (A 128*80 + B 256*80) + sred
#define STAGE_BYTES (BM * ROWB + BN * ROWB)        // 30720
#define SM_SRED     (NSTAGE * STAGE_BYTES)         // 122880
#define SMEM_TOTAL  (SM_SRED + BM * 8 * 4)         // 126976

// Scratch
__device__ uint8_t g_q[3][(size_t)N_ROWS * D_DIM];
__device__ float g_partial[(size_t)N_ROWS * CT_N];
__device__ float g_diag[N_ROWS];

// ---------------------------------------------------------------------------
__device__ __forceinline__ uint32_t smem_u32(const void* p) {
    uint32_t a;
    asm("{ .reg .u64 t; cvta.to.shared.u64 t, %1; cvt.u32.u64 %0, t; }"
        : "=r"(a) : "l"(p));
    return a;
}

#define LDSM_X4(r, addr) \
    asm volatile("ldmatrix.sync.aligned.m8n8.x4.shared.b16 {%0,%1,%2,%3}, [%4];" \
                 : "=r"((r)[0]), "=r"((r)[1]), "=r"((r)[2]), "=r"((r)[3]) : "r"(addr))

#define MMA_FP8(d, a, b) \
    asm volatile("mma.sync.aligned.m16n8k32.row.col.f32.e4m3.e4m3.f32 " \
                 "{%0,%1,%2,%3}, {%4,%5,%6,%7}, {%8,%9}, {%0,%1,%2,%3};" \
                 : "+f"((d)[0]), "+f"((d)[1]), "+f"((d)[2]), "+f"((d)[3]) \
                 : "r"((a)[0]), "r"((a)[1]), "r"((a)[2]), "r"((a)[3]), \
                   "r"((b)[0]), "r"((b)[1]))

#define CP_ASYNC16(so, gp) \
    asm volatile("cp.async.cg.shared.global [%0], [%1], 16;" \
                 :: "r"(so), "l"(__cvta_generic_to_global(gp)))
#define CP_COMMIT()  asm volatile("cp.async.commit_group;" ::: "memory")
#define CP_WAIT(n)   asm volatile("cp.async.wait_group %0;" :: "n"(n) : "memory")

__device__ __forceinline__ uint32_t pack4_e4m3(float4 v) {
    uint16_t lo, hi;
    asm("cvt.rn.satfinite.e4m3x2.f32 %0, %1, %2;" : "=h"(lo) : "f"(v.y), "f"(v.x));
    asm("cvt.rn.satfinite.e4m3x2.f32 %0, %1, %2;" : "=h"(hi) : "f"(v.w), "f"(v.z));
    return (uint32_t)lo | ((uint32_t)hi << 16);
}

// ---------------------------------------------------------------------------
// Kernel 1: row norms + normalize (+ 1/TEMP into x) + scale + e4m3 convert.
// ---------------------------------------------------------------------------
__global__ void __launch_bounds__(256) norm_convert_kernel(const float* __restrict__ x,
                                                           const float* __restrict__ t,
                                                           const float* __restrict__ h) {
    int warp = (blockIdx.x * blockDim.x + threadIdx.x) >> 5;
    int lane = threadIdx.x & 31;
    if (warp >= 3 * N_ROWS) return;
    int mat = warp / N_ROWS;
    int row = warp - mat * N_ROWS;
    const float* src = (mat == 0) ? x : (mat == 1 ? t : h);
    const float4* p = (const float4*)(src + (size_t)row * D_DIM);
    float4 v[8];
    float s = 0.f;
#pragma unroll
    for (int i = 0; i < 8; i++) {
        v[i] = p[lane + i * 32];
        s += v[i].x * v[i].x + v[i].y * v[i].y + v[i].z * v[i].z + v[i].w * v[i].w;
    }
#pragma unroll
    for (int o = 16; o; o >>= 1) s += __shfl_xor_sync(0xffffffffu, s, o);
    float inv = 1.0f / fmaxf(sqrtf(s), EPS_N);
    float sc = ((mat == 0) ? inv * TEMP_INV : inv) * QSCALE;
    uint32_t* dst = (uint32_t*)(&g_q[mat][(size_t)row * D_DIM]);
#pragma unroll
    for (int i = 0; i < 8; i++) {
        float4 w;
        w.x = v[i].x * sc; w.y = v[i].y * sc; w.z = v[i].z * sc; w.w = v[i].w * sc;
        dst[lane + i * 32] = pack4_e4m3(w);
    }
}

// ---------------------------------------------------------------------------
// Kernel 2: e4m3 GEMM, CTA 128x256, 16 warps (2Mx8N), warp tile 64x32,
// 4-stage cp.async pipeline, fused exp epilogue.
// ---------------------------------------------------------------------------
__global__ void __launch_bounds__(NTHREADS, 1) sim_fp8_kernel() {
    extern __shared__ __align__(16) char dsm[];
    const int tid = threadIdx.x;
    const int lane = tid & 31;
    const int wid = tid >> 5;
    const int wm = wid & 1;            // 0..1 -> 64 rows
    const int wn = wid >> 1;           // 0..7 -> 32 cols

    const int ct = blockIdx.x;         // 0..31
    const int rt = blockIdx.y;         // 0..31
    const int rbase = rt * BM;
    const int cbase = ct * BN;
    const bool isNeg = (cbase >= N_ROWS);
    const uint8_t* Bmat = isNeg ? g_q[2] : g_q[1];
    const int cloc = isNeg ? (cbase - N_ROWS) : cbase;

    const uint8_t* Ag = g_q[0] + (size_t)rbase * D_DIM;
    const uint8_t* Bg = Bmat + (size_t)cloc * D_DIM;

    // Load slots: A = 512 slots (1/thread); B = 1024 slots (2/thread)
    const int ra = tid >> 2, sa = (tid & 3) * 16;
    uint32_t aSm, aGo;
    aSm = (uint32_t)(ra * ROWB + sa);
    aGo = (uint32_t)(ra * D_DIM + sa);
    uint32_t bSm[2], bGo[2];
#pragma unroll
    for (int q = 0; q < 2; q++) {
        int slot = tid + q * NTHREADS;
        int r = slot >> 2, sg = (slot & 3) * 16;
        bSm[q] = (uint32_t)(BM * ROWB + r * ROWB + sg);
        bGo[q] = (uint32_t)(r * D_DIM + sg);
    }
    uint32_t stageBase[NSTAGE];
#pragma unroll
    for (int s = 0; s < NSTAGE; s++) stageBase[s] = smem_u32(dsm + s * STAGE_BYTES);

#define LOAD_CHUNK(c, st)                                       \
    do {                                                        \
        const uint32_t k0 = (c) * BK;                           \
        const uint32_t sb_ = stageBase[st];                     \
        CP_ASYNC16(sb_ + aSm, Ag + aGo + k0);                   \
        CP_ASYNC16(sb_ + bSm[0], Bg + bGo[0] + k0);             \
        CP_ASYNC16(sb_ + bSm[1], Bg + bGo[1] + k0);             \
        CP_COMMIT();                                            \
    } while (0)

    float acc[4][4][4];
#pragma unroll
    for (int i = 0; i < 4; i++)
#pragma unroll
        for (int j = 0; j < 4; j++)
#pragma unroll
            for (int q = 0; q < 4; q++) acc[i][j][q] = 0.f;

    LOAD_CHUNK(0, 0);
    LOAD_CHUNK(1, 1);
    LOAD_CHUNK(2, 2);

    // ldmatrix lane addressing (byte-identical to HW-verified rounds 3/4)
    const int aRow = lane & 15;
    const int aSeg = (lane >> 4) * 16;
    const int bRow = ((lane >> 4) ? 8 : 0) + (lane & 7);
    const int bSeg = ((lane >> 3) & 1) * 16;

    for (int c = 0; c < NKC; c++) {
        if (c + 3 < NKC) LOAD_CHUNK(c + 3, (c + 3) & 3);
        else CP_COMMIT();                 // empty group keeps FIFO arithmetic uniform
        CP_WAIT(3);                       // oldest (chunk c) has landed
        __syncthreads();

        const uint32_t aB = stageBase[c & 3];
        const uint32_t bB = aB + BM * ROWB;
#pragma unroll
        for (int ks = 0; ks < 2; ks++) {  // two 32B k-slices per 64B chunk
            const int kso = ks * 32;
            uint32_t afr[4][4], bfr[4][2];
#pragma unroll
            for (int mt = 0; mt < 4; mt++) {
                int row = wm * 64 + mt * 16 + aRow;
                LDSM_X4(afr[mt], aB + row * ROWB + kso + aSeg);
            }
#pragma unroll
            for (int np = 0; np < 2; np++) {
                int nrow = wn * 32 + np * 16 + bRow;
                uint32_t r[4];
                LDSM_X4(r, bB + nrow * ROWB + kso + bSeg);
                bfr[np * 2 + 0][0] = r[0];
                bfr[np * 2 + 0][1] = r[1];
                bfr[np * 2 + 1][0] = r[2];
                bfr[np * 2 + 1][1] = r[3];
            }
#pragma unroll
            for (int mt = 0; mt < 4; mt++)
#pragma unroll
                for (int nt = 0; nt < 4; nt++) MMA_FP8(acc[mt][nt], afr[mt], bfr[nt]);
        }
        __syncthreads();
    }

    // Epilogue
    const int g = lane >> 2;
    const int t2 = (lane & 3) * 2;
    const int diagOff = isNeg ? N_ROWS : 0;
    float* sred = (float*)(dsm + SM_SRED);

#pragma unroll
    for (int mt = 0; mt < 4; mt++) {
        const int gi0 = rbase + wm * 64 + mt * 16 + g;
        const int gi1 = gi0 + 8;
        const int d0 = gi0 + diagOff;
        const int d1 = gi1 + diagOff;
        float s0 = 0.f, s1 = 0.f;
#pragma unroll
        for (int nt = 0; nt < 4; nt++) {
            const int gc = cbase + wn * 32 + nt * 8 + t2;
            float v0 = acc[mt][nt][0] * ISC2;
            float v1 = acc[mt][nt][1] * ISC2;
            float v2 = acc[mt][nt][2] * ISC2;
            float v3 = acc[mt][nt][3] * ISC2;
            if (gc == d0)     { if (isNeg) v0 += 1.f; else g_diag[gi0] = v0; }
            if (gc + 1 == d0) { if (isNeg) v1 += 1.f; else g_diag[gi0] = v1; }
            if (gc == d1)     { if (isNeg) v2 += 1.f; else g_diag[gi1] = v2; }
            if (gc + 1 == d1) { if (isNeg) v3 += 1.f; else g_diag[gi1] = v3; }
            s0 += __expf(v0) + __expf(v1);
            s1 += __expf(v2) + __expf(v3);
        }
        s0 += __shfl_xor_sync(0xffffffffu, s0, 1);
        s0 += __shfl_xor_sync(0xffffffffu, s0, 2);
        s1 += __shfl_xor_sync(0xffffffffu, s1, 1);
        s1 += __shfl_xor_sync(0xffffffffu, s1, 2);
        if ((lane & 3) == 0) {
            sred[(wm * 64 + mt * 16 + g) * 8 + wn] = s0;
            sred[(wm * 64 + mt * 16 + g + 8) * 8 + wn] = s1;
        }
    }
    __syncthreads();
    if (tid < BM) {
        float s = 0.f;
#pragma unroll
        for (int q = 0; q < 8; q++) s += sred[tid * 8 + q];
        g_partial[(size_t)(rbase + tid) * CT_N + ct] = s;
    }
}

// ---------------------------------------------------------------------------
// Kernel 3: finalize (float4 partial reads).
// ---------------------------------------------------------------------------
__global__ void __launch_bounds__(256) finalize_kernel(float* __restrict__ out) {
    __shared__ float sm[256];
    const int tid = threadIdx.x;
    float local = 0.f;
    for (int row = tid; row < N_ROWS; row += 256) {
        const float4* p = (const float4*)&g_partial[(size_t)row * CT_N];
        float s = 0.f;
#pragma unroll
        for (int c = 0; c < CT_N / 4; c++) {
            float4 v = p[c];
            s += v.x + v.y + v.z + v.w;
        }
        local += logf(s) - g_diag[row];
    }
    sm[tid] = local;
    __syncthreads();
#pragma unroll
    for (int o = 128; o; o >>= 1) {
        if (tid < o) sm[tid] += sm[tid + o];
        __syncthreads();
    }
    if (tid == 0) out[0] = sm[0] * (1.0f / N_ROWS);
}

// ---------------------------------------------------------------------------
extern "C" void kernel_launch(void* const* d_in, const int* in_sizes, int n_in,
                              void* d_out, int out_size) {
    const float* x = (const float*)d_in[0];
    const float* t = (const float*)d_in[1];
    const float* h = (const float*)d_in[2];
    float* out = (float*)d_out;

    cudaFuncSetAttribute(sim_fp8_kernel,
                         cudaFuncAttributeMaxDynamicSharedMemorySize, SMEM_TOTAL);

    norm_convert_kernel<<<(3 * N_ROWS) / 8, 256>>>(x, t, h);

    dim3 grid(CT_N, RT_N);
    sim_fp8_kernel<<<grid, NTHREADS, SMEM_TOTAL>>>();

    finalize_kernel<<<1, 256>>>(out);
}

// round 6
// speedup vs baseline: 11.6855x; 1.1760x over previous
#include <cuda_runtime.h>
#include <cuda_bf16.h>
#include <cuda_fp16.h>
#include <math.h>
#include <stdint.h>

#define N_ROWS   4096
#define D_DIM    1024
#define TEMP_INV 20.0f
#define EPS_N    1e-8f
#define QSCALE   16.0f
#define ISC2     (1.0f / (QSCALE * QSCALE))

// GEMM tiling (fp8 e4m3; K in bytes == elements)
#define BM 128
#define BN 256
#define BK 64
#define NKC (D_DIM / BK)         // 16 chunks
#define NSTAGE 4
#define CT_N (2 * N_ROWS / BN)   // 32 col tiles
#define RT_N (N_ROWS / BM)       // 32 row tiles
#define ROWB 80                  // padded smem row stride (64B data + 16B pad)
#define NTHREADS 512

#define STAGE_BYTES (BM * ROWB + BN * ROWB)        // 30720
#define SM_SRED     (NSTAGE * STAGE_BYTES)         // 122880
#define SMEM_TOTAL  (SM_SRED + BM * 8 * 4)         // 126976

// Scratch
__device__ uint8_t g_q[3][(size_t)N_ROWS * D_DIM];
__device__ float g_partial[(size_t)N_ROWS * CT_N];
__device__ float g_diag[N_ROWS];
__device__ float g_rowloss[N_ROWS];

// ---------------------------------------------------------------------------
__device__ __forceinline__ uint32_t smem_u32(const void* p) {
    uint32_t a;
    asm("{ .reg .u64 t; cvta.to.shared.u64 t, %1; cvt.u32.u64 %0, t; }"
        : "=r"(a) : "l"(p));
    return a;
}

#define LDSM_X4(r, addr) \
    asm volatile("ldmatrix.sync.aligned.m8n8.x4.shared.b16 {%0,%1,%2,%3}, [%4];" \
                 : "=r"((r)[0]), "=r"((r)[1]), "=r"((r)[2]), "=r"((r)[3]) : "r"(addr))

// fp8 e4m3 MMA with f16 accumulators: d = {h2 lo(rows g), h2 hi(rows g+8)}
#define MMA_FP8_H(d, a, b) \
    asm volatile("mma.sync.aligned.m16n8k32.row.col.f16.e4m3.e4m3.f16 " \
                 "{%0,%1}, {%2,%3,%4,%5}, {%6,%7}, {%0,%1};" \
                 : "+r"((d)[0]), "+r"((d)[1]) \
                 : "r"((a)[0]), "r"((a)[1]), "r"((a)[2]), "r"((a)[3]), \
                   "r"((b)[0]), "r"((b)[1]))

#define CP_ASYNC16(so, gp) \
    asm volatile("cp.async.cg.shared.global [%0], [%1], 16;" \
                 :: "r"(so), "l"(__cvta_generic_to_global(gp)))
#define CP_COMMIT()  asm volatile("cp.async.commit_group;" ::: "memory")
#define CP_WAIT(n)   asm volatile("cp.async.wait_group %0;" :: "n"(n) : "memory")

__device__ __forceinline__ uint32_t pack4_e4m3(float4 v) {
    uint16_t lo, hi;
    asm("cvt.rn.satfinite.e4m3x2.f32 %0, %1, %2;" : "=h"(lo) : "f"(v.y), "f"(v.x));
    asm("cvt.rn.satfinite.e4m3x2.f32 %0, %1, %2;" : "=h"(hi) : "f"(v.w), "f"(v.z));
    return (uint32_t)lo | ((uint32_t)hi << 16);
}

// ---------------------------------------------------------------------------
// Kernel 1: row norms + normalize (+ 1/TEMP into x) + scale + e4m3 convert.
// ---------------------------------------------------------------------------
__global__ void __launch_bounds__(256) norm_convert_kernel(const float* __restrict__ x,
                                                           const float* __restrict__ t,
                                                           const float* __restrict__ h) {
    int warp = (blockIdx.x * blockDim.x + threadIdx.x) >> 5;
    int lane = threadIdx.x & 31;
    if (warp >= 3 * N_ROWS) return;
    int mat = warp / N_ROWS;
    int row = warp - mat * N_ROWS;
    const float* src = (mat == 0) ? x : (mat == 1 ? t : h);
    const float4* p = (const float4*)(src + (size_t)row * D_DIM);
    float4 v[8];
    float s = 0.f;
#pragma unroll
    for (int i = 0; i < 8; i++) {
        v[i] = p[lane + i * 32];
        s += v[i].x * v[i].x + v[i].y * v[i].y + v[i].z * v[i].z + v[i].w * v[i].w;
    }
#pragma unroll
    for (int o = 16; o; o >>= 1) s += __shfl_xor_sync(0xffffffffu, s, o);
    float inv = 1.0f / fmaxf(sqrtf(s), EPS_N);
    float sc = ((mat == 0) ? inv * TEMP_INV : inv) * QSCALE;
    uint32_t* dst = (uint32_t*)(&g_q[mat][(size_t)row * D_DIM]);
#pragma unroll
    for (int i = 0; i < 8; i++) {
        float4 w;
        w.x = v[i].x * sc; w.y = v[i].y * sc; w.z = v[i].z * sc; w.w = v[i].w * sc;
        dst[lane + i * 32] = pack4_e4m3(w);
    }
}

// ---------------------------------------------------------------------------
// Kernel 2: e4m3 GEMM (f16 acc), CTA 128x256, 16 warps (2Mx8N), warp 64x32,
// 4-stage cp.async pipeline with ONE sync per chunk, fused exp epilogue.
// ---------------------------------------------------------------------------
__global__ void __launch_bounds__(NTHREADS, 1) sim_fp8_kernel() {
    extern __shared__ __align__(16) char dsm[];
    const int tid = threadIdx.x;
    const int lane = tid & 31;
    const int wid = tid >> 5;
    const int wm = wid & 1;            // 0..1 -> 64 rows
    const int wn = wid >> 1;           // 0..7 -> 32 cols

    const int ct = blockIdx.x;         // 0..31
    const int rt = blockIdx.y;         // 0..31
    const int rbase = rt * BM;
    const int cbase = ct * BN;
    const bool isNeg = (cbase >= N_ROWS);
    const uint8_t* Bmat = isNeg ? g_q[2] : g_q[1];
    const int cloc = isNeg ? (cbase - N_ROWS) : cbase;

    const uint8_t* Ag = g_q[0] + (size_t)rbase * D_DIM;
    const uint8_t* Bg = Bmat + (size_t)cloc * D_DIM;

    const int ra = tid >> 2, sa = (tid & 3) * 16;
    const uint32_t aSm = (uint32_t)(ra * ROWB + sa);
    const uint32_t aGo = (uint32_t)(ra * D_DIM + sa);
    uint32_t bSm[2], bGo[2];
#pragma unroll
    for (int q = 0; q < 2; q++) {
        int slot = tid + q * NTHREADS;
        int r = slot >> 2, sg = (slot & 3) * 16;
        bSm[q] = (uint32_t)(BM * ROWB + r * ROWB + sg);
        bGo[q] = (uint32_t)(r * D_DIM + sg);
    }
    uint32_t stageBase[NSTAGE];
#pragma unroll
    for (int s = 0; s < NSTAGE; s++) stageBase[s] = smem_u32(dsm + s * STAGE_BYTES);

#define LOAD_CHUNK(c, st)                                       \
    do {                                                        \
        const uint32_t k0 = (c) * BK;                           \
        const uint32_t sb_ = stageBase[st];                     \
        CP_ASYNC16(sb_ + aSm, Ag + aGo + k0);                   \
        CP_ASYNC16(sb_ + bSm[0], Bg + bGo[0] + k0);             \
        CP_ASYNC16(sb_ + bSm[1], Bg + bGo[1] + k0);             \
        CP_COMMIT();                                            \
    } while (0)

    uint32_t acc[4][4][2];      // f16x2 accumulators
#pragma unroll
    for (int i = 0; i < 4; i++)
#pragma unroll
        for (int j = 0; j < 4; j++) { acc[i][j][0] = 0u; acc[i][j][1] = 0u; }

    LOAD_CHUNK(0, 0);
    LOAD_CHUNK(1, 1);
    LOAD_CHUNK(2, 2);

    // ldmatrix lane addressing (HW-verified rounds 3-5)
    const int aRow = lane & 15;
    const int aSeg = (lane >> 4) * 16;
    const int bRow = ((lane >> 4) ? 8 : 0) + (lane & 7);
    const int bSeg = ((lane >> 3) & 1) * 16;

    for (int c = 0; c < NKC; c++) {
        CP_WAIT(2);                      // chunk c landed (3 groups in flight max)
        __syncthreads();                 // publish stage c; protect stage reuse
        if (c + 3 < NKC) LOAD_CHUNK(c + 3, (c + 3) & 3);
        else CP_COMMIT();                // keep group-count arithmetic uniform

        const uint32_t aB = stageBase[c & 3];
        const uint32_t bB = aB + BM * ROWB;
#pragma unroll
        for (int ks = 0; ks < 2; ks++) {
            const int kso = ks * 32;
            uint32_t afr[4][4], bfr[4][2];
#pragma unroll
            for (int mt = 0; mt < 4; mt++) {
                int row = wm * 64 + mt * 16 + aRow;
                LDSM_X4(afr[mt], aB + row * ROWB + kso + aSeg);
            }
#pragma unroll
            for (int np = 0; np < 2; np++) {
                int nrow = wn * 32 + np * 16 + bRow;
                uint32_t r[4];
                LDSM_X4(r, bB + nrow * ROWB + kso + bSeg);
                bfr[np * 2 + 0][0] = r[0];
                bfr[np * 2 + 0][1] = r[1];
                bfr[np * 2 + 1][0] = r[2];
                bfr[np * 2 + 1][1] = r[3];
            }
#pragma unroll
            for (int mt = 0; mt < 4; mt++)
#pragma unroll
                for (int nt = 0; nt < 4; nt++) MMA_FP8_H(acc[mt][nt], afr[mt], bfr[nt]);
        }
    }
    __syncthreads();   // last chunk consumed before epilogue smem reuse ordering

    // Epilogue: unpack f16 acc, rescale, diag fixup, exp, per-row sums.
    const int g = lane >> 2;
    const int t2 = (lane & 3) * 2;
    const int diagOff = isNeg ? N_ROWS : 0;
    float* sred = (float*)(dsm + SM_SRED);

#pragma unroll
    for (int mt = 0; mt < 4; mt++) {
        const int gi0 = rbase + wm * 64 + mt * 16 + g;
        const int gi1 = gi0 + 8;
        const int d0 = gi0 + diagOff;
        const int d1 = gi1 + diagOff;
        float s0 = 0.f, s1 = 0.f;
#pragma unroll
        for (int nt = 0; nt < 4; nt++) {
            const int gc = cbase + wn * 32 + nt * 8 + t2;
            __half2 lo = *(__half2*)&acc[mt][nt][0];
            __half2 hi = *(__half2*)&acc[mt][nt][1];
            float v0 = __half2float(lo.x) * ISC2;
            float v1 = __half2float(lo.y) * ISC2;
            float v2 = __half2float(hi.x) * ISC2;
            float v3 = __half2float(hi.y) * ISC2;
            if (gc == d0)     { if (isNeg) v0 += 1.f; else g_diag[gi0] = v0; }
            if (gc + 1 == d0) { if (isNeg) v1 += 1.f; else g_diag[gi0] = v1; }
            if (gc == d1)     { if (isNeg) v2 += 1.f; else g_diag[gi1] = v2; }
            if (gc + 1 == d1) { if (isNeg) v3 += 1.f; else g_diag[gi1] = v3; }
            s0 += __expf(v0) + __expf(v1);
            s1 += __expf(v2) + __expf(v3);
        }
        s0 += __shfl_xor_sync(0xffffffffu, s0, 1);
        s0 += __shfl_xor_sync(0xffffffffu, s0, 2);
        s1 += __shfl_xor_sync(0xffffffffu, s1, 1);
        s1 += __shfl_xor_sync(0xffffffffu, s1, 2);
        if ((lane & 3) == 0) {
            sred[(wm * 64 + mt * 16 + g) * 8 + wn] = s0;
            sred[(wm * 64 + mt * 16 + g + 8) * 8 + wn] = s1;
        }
    }
    __syncthreads();
    if (tid < BM) {
        float s = 0.f;
#pragma unroll
        for (int q = 0; q < 8; q++) s += sred[tid * 8 + q];
        g_partial[(size_t)(rbase + tid) * CT_N + ct] = s;
    }
}

// ---------------------------------------------------------------------------
// Kernel 3a: per-row loss, fully parallel (16 CTAs x 256 threads = 1 row/thread)
// ---------------------------------------------------------------------------
__global__ void __launch_bounds__(256) rowloss_kernel() {
    const int row = blockIdx.x * 256 + threadIdx.x;
    const float4* p = (const float4*)&g_partial[(size_t)row * CT_N];
    float s = 0.f;
#pragma unroll
    for (int c = 0; c < CT_N / 4; c++) {
        float4 v = p[c];
        s += v.x + v.y + v.z + v.w;
    }
    g_rowloss[row] = logf(s) - g_diag[row];
}

// ---------------------------------------------------------------------------
// Kernel 3b: reduce 4096 row losses -> scalar mean
// ---------------------------------------------------------------------------
__global__ void __launch_bounds__(256) reduce_kernel(float* __restrict__ out) {
    __shared__ float sm[256];
    const int tid = threadIdx.x;
    const float4* p = (const float4*)g_rowloss;
    float local = 0.f;
#pragma unroll
    for (int i = 0; i < 4; i++) {
        float4 v = p[tid + i * 256];
        local += v.x + v.y + v.z + v.w;
    }
    sm[tid] = local;
    __syncthreads();
#pragma unroll
    for (int o = 128; o; o >>= 1) {
        if (tid < o) sm[tid] += sm[tid + o];
        __syncthreads();
    }
    if (tid == 0) out[0] = sm[0] * (1.0f / N_ROWS);
}

// ---------------------------------------------------------------------------
extern "C" void kernel_launch(void* const* d_in, const int* in_sizes, int n_in,
                              void* d_out, int out_size) {
    const float* x = (const float*)d_in[0];
    const float* t = (const float*)d_in[1];
    const float* h = (const float*)d_in[2];
    float* out = (float*)d_out;

    cudaFuncSetAttribute(sim_fp8_kernel,
                         cudaFuncAttributeMaxDynamicSharedMemorySize, SMEM_TOTAL);

    norm_convert_kernel<<<(3 * N_ROWS) / 8, 256>>>(x, t, h);

    dim3 grid(CT_N, RT_N);
    sim_fp8_kernel<<<grid, NTHREADS, SMEM_TOTAL>>>();

    rowloss_kernel<<<N_ROWS / 256, 256>>>();
    reduce_kernel<<<1, 256>>>(out);
}

// round 7
// speedup vs baseline: 12.0655x; 1.0325x over previous
#include <cuda_runtime.h>
#include <cuda_bf16.h>
#include <cuda_fp16.h>
#include <math.h>
#include <stdint.h>

#define N_ROWS   4096
#define D_DIM    1024
#define TEMP_INV 20.0f
#define EPS_N    1e-8f
#define QSCALE   16.0f
#define ISC2     (1.0f / (QSCALE * QSCALE))

// GEMM tiling (fp8 e4m3; K in bytes == elements)
#define BM 128
#define BN 128
#define BK 128
#define NKC (D_DIM / BK)         // 8 chunks
#define NSTAGE 3
#define CT_N (2 * N_ROWS / BN)   // 64 col tiles
#define RT_N (N_ROWS / BM)       // 32 row tiles
#define ROWB 144                 // 128B data + 16B pad
#define NTHREADS 256

#define STAGE_BYTES ((BM + BN) * ROWB)             // 36864
#define SM_SRED     (NSTAGE * STAGE_BYTES)         // 110592
#define SMEM_TOTAL  (SM_SRED + BM * 4 * 4)         // 112640 (2 CTAs/SM fit)

// Scratch
__device__ uint8_t g_q[3][(size_t)N_ROWS * D_DIM];
__device__ float g_partial[(size_t)N_ROWS * CT_N];
__device__ float g_diag[N_ROWS];
__device__ float g_rowloss[N_ROWS];

// ---------------------------------------------------------------------------
__device__ __forceinline__ uint32_t smem_u32(const void* p) {
    uint32_t a;
    asm("{ .reg .u64 t; cvta.to.shared.u64 t, %1; cvt.u32.u64 %0, t; }"
        : "=r"(a) : "l"(p));
    return a;
}

#define LDSM_X4(r, addr) \
    asm volatile("ldmatrix.sync.aligned.m8n8.x4.shared.b16 {%0,%1,%2,%3}, [%4];" \
                 : "=r"((r)[0]), "=r"((r)[1]), "=r"((r)[2]), "=r"((r)[3]) : "r"(addr))

#define MMA_FP8_H(d, a, b) \
    asm volatile("mma.sync.aligned.m16n8k32.row.col.f16.e4m3.e4m3.f16 " \
                 "{%0,%1}, {%2,%3,%4,%5}, {%6,%7}, {%0,%1};" \
                 : "+r"((d)[0]), "+r"((d)[1]) \
                 : "r"((a)[0]), "r"((a)[1]), "r"((a)[2]), "r"((a)[3]), \
                   "r"((b)[0]), "r"((b)[1]))

#define CP_ASYNC16(so, gp) \
    asm volatile("cp.async.cg.shared.global [%0], [%1], 16;" \
                 :: "r"(so), "l"(__cvta_generic_to_global(gp)))
#define CP_COMMIT()  asm volatile("cp.async.commit_group;" ::: "memory")
#define CP_WAIT(n)   asm volatile("cp.async.wait_group %0;" :: "n"(n) : "memory")

__device__ __forceinline__ uint32_t pack4_e4m3(float4 v) {
    uint16_t lo, hi;
    asm("cvt.rn.satfinite.e4m3x2.f32 %0, %1, %2;" : "=h"(lo) : "f"(v.y), "f"(v.x));
    asm("cvt.rn.satfinite.e4m3x2.f32 %0, %1, %2;" : "=h"(hi) : "f"(v.w), "f"(v.z));
    return (uint32_t)lo | ((uint32_t)hi << 16);
}

// ---------------------------------------------------------------------------
// Kernel 1: row norms + normalize (+ 1/TEMP into x) + scale + e4m3 convert.
// ---------------------------------------------------------------------------
__global__ void __launch_bounds__(256) norm_convert_kernel(const float* __restrict__ x,
                                                           const float* __restrict__ t,
                                                           const float* __restrict__ h) {
    int warp = (blockIdx.x * blockDim.x + threadIdx.x) >> 5;
    int lane = threadIdx.x & 31;
    if (warp >= 3 * N_ROWS) return;
    int mat = warp / N_ROWS;
    int row = warp - mat * N_ROWS;
    const float* src = (mat == 0) ? x : (mat == 1 ? t : h);
    const float4* p = (const float4*)(src + (size_t)row * D_DIM);
    float4 v[8];
    float s = 0.f;
#pragma unroll
    for (int i = 0; i < 8; i++) {
        v[i] = p[lane + i * 32];
        s += v[i].x * v[i].x + v[i].y * v[i].y + v[i].z * v[i].z + v[i].w * v[i].w;
    }
#pragma unroll
    for (int o = 16; o; o >>= 1) s += __shfl_xor_sync(0xffffffffu, s, o);
    float inv = 1.0f / fmaxf(sqrtf(s), EPS_N);
    float sc = ((mat == 0) ? inv * TEMP_INV : inv) * QSCALE;
    uint32_t* dst = (uint32_t*)(&g_q[mat][(size_t)row * D_DIM]);
#pragma unroll
    for (int i = 0; i < 8; i++) {
        float4 w;
        w.x = v[i].x * sc; w.y = v[i].y * sc; w.z = v[i].z * sc; w.w = v[i].w * sc;
        dst[lane + i * 32] = pack4_e4m3(w);
    }
}

// ---------------------------------------------------------------------------
// Kernel 2: e4m3 GEMM (f16 acc), CTA 128x128, 256 threads (2Mx4N warps),
// BK=128, 3-stage cp.async, fragment double-buffering, 2 CTAs/SM.
// ---------------------------------------------------------------------------
__global__ void __launch_bounds__(NTHREADS, 2) sim_fp8_kernel() {
    extern __shared__ __align__(16) char dsm[];
    const int tid = threadIdx.x;
    const int lane = tid & 31;
    const int wid = tid >> 5;
    const int wm = wid & 1;            // 0..1 -> 64 rows
    const int wn = wid >> 1;           // 0..3 -> 32 cols

    const int ct = blockIdx.x;         // 0..63
    const int rt = blockIdx.y;         // 0..31
    const int rbase = rt * BM;
    const int cbase = ct * BN;
    const bool isNeg = (cbase >= N_ROWS);
    const uint8_t* Bmat = isNeg ? g_q[2] : g_q[1];
    const int cloc = isNeg ? (cbase - N_ROWS) : cbase;

    const uint8_t* Ag = g_q[0] + (size_t)rbase * D_DIM;
    const uint8_t* Bg = Bmat + (size_t)cloc * D_DIM;

    // cp.async slots: A = 128 rows x 8 segs = 1024 (4/thread); B same.
    uint32_t aSm[4], aGo[4], bSm[4], bGo[4];
#pragma unroll
    for (int q = 0; q < 4; q++) {
        int slot = tid + q * NTHREADS;
        int r = slot >> 3, sg = (slot & 7) * 16;
        aSm[q] = (uint32_t)(r * ROWB + sg);
        aGo[q] = (uint32_t)(r * D_DIM + sg);
        bSm[q] = (uint32_t)(BM * ROWB + r * ROWB + sg);
        bGo[q] = (uint32_t)(r * D_DIM + sg);
    }
    uint32_t stageBase[NSTAGE];
#pragma unroll
    for (int s = 0; s < NSTAGE; s++) stageBase[s] = smem_u32(dsm + s * STAGE_BYTES);

#define LOAD_CHUNK(c, st)                                       \
    do {                                                        \
        const uint32_t k0 = (c) * BK;                           \
        const uint32_t sb_ = stageBase[st];                     \
        CP_ASYNC16(sb_ + aSm[0], Ag + aGo[0] + k0);             \
        CP_ASYNC16(sb_ + aSm[1], Ag + aGo[1] + k0);             \
        CP_ASYNC16(sb_ + aSm[2], Ag + aGo[2] + k0);             \
        CP_ASYNC16(sb_ + aSm[3], Ag + aGo[3] + k0);             \
        CP_ASYNC16(sb_ + bSm[0], Bg + bGo[0] + k0);             \
        CP_ASYNC16(sb_ + bSm[1], Bg + bGo[1] + k0);             \
        CP_ASYNC16(sb_ + bSm[2], Bg + bGo[2] + k0);             \
        CP_ASYNC16(sb_ + bSm[3], Bg + bGo[3] + k0);             \
        CP_COMMIT();                                            \
    } while (0)

    uint32_t acc[4][4][2];
#pragma unroll
    for (int i = 0; i < 4; i++)
#pragma unroll
        for (int j = 0; j < 4; j++) { acc[i][j][0] = 0u; acc[i][j][1] = 0u; }

    LOAD_CHUNK(0, 0);
    LOAD_CHUNK(1, 1);

    // ldmatrix lane addressing (HW-verified rounds 3-6)
    const int aRow = lane & 15;
    const int aSeg = (lane >> 4) * 16;
    const int bRow = ((lane >> 4) ? 8 : 0) + (lane & 7);
    const int bSeg = ((lane >> 3) & 1) * 16;

    uint32_t afr[2][4][4], bfr[2][4][2];

#define LOAD_FRAGS(buf_, base_, kso_)                                        \
    do {                                                                     \
        _Pragma("unroll")                                                    \
        for (int mt = 0; mt < 4; mt++) {                                     \
            int row = wm * 64 + mt * 16 + aRow;                              \
            LDSM_X4(afr[buf_][mt], (base_) + row * ROWB + (kso_) + aSeg);    \
        }                                                                    \
        _Pragma("unroll")                                                    \
        for (int np = 0; np < 2; np++) {                                     \
            int nrow = wn * 32 + np * 16 + bRow;                             \
            uint32_t r_[4];                                                  \
            LDSM_X4(r_, (base_) + BM * ROWB + nrow * ROWB + (kso_) + bSeg);  \
            bfr[buf_][np * 2 + 0][0] = r_[0];                                \
            bfr[buf_][np * 2 + 0][1] = r_[1];                                \
            bfr[buf_][np * 2 + 1][0] = r_[2];                                \
            bfr[buf_][np * 2 + 1][1] = r_[3];                                \
        }                                                                    \
    } while (0)

    for (int c = 0; c < NKC; c++) {
        CP_WAIT(1);                      // chunk c landed
        __syncthreads();                 // publish stage c; protect reuse of stage (c+2)%3
        if (c + 2 < NKC) LOAD_CHUNK(c + 2, (c + 2) % 3);
        else CP_COMMIT();                // keep group-count arithmetic uniform

        const uint32_t sBase = stageBase[c % 3];
        LOAD_FRAGS(0, sBase, 0);
#pragma unroll
        for (int ks = 0; ks < 4; ks++) { // four 32B k-slices per 128B chunk
            const int cur = ks & 1;
            if (ks < 3) LOAD_FRAGS(cur ^ 1, sBase, (ks + 1) * 32);
#pragma unroll
            for (int mt = 0; mt < 4; mt++)
#pragma unroll
                for (int nt = 0; nt < 4; nt++)
                    MMA_FP8_H(acc[mt][nt], afr[cur][mt], bfr[cur][nt]);
        }
    }

    // Epilogue
    const int g = lane >> 2;
    const int t2 = (lane & 3) * 2;
    const int diagOff = isNeg ? N_ROWS : 0;
    float* sred = (float*)(dsm + SM_SRED);

#pragma unroll
    for (int mt = 0; mt < 4; mt++) {
        const int gi0 = rbase + wm * 64 + mt * 16 + g;
        const int gi1 = gi0 + 8;
        const int d0 = gi0 + diagOff;
        const int d1 = gi1 + diagOff;
        float s0 = 0.f, s1 = 0.f;
#pragma unroll
        for (int nt = 0; nt < 4; nt++) {
            const int gc = cbase + wn * 32 + nt * 8 + t2;
            __half2 lo = *(__half2*)&acc[mt][nt][0];
            __half2 hi = *(__half2*)&acc[mt][nt][1];
            float v0 = __half2float(lo.x) * ISC2;
            float v1 = __half2float(lo.y) * ISC2;
            float v2 = __half2float(hi.x) * ISC2;
            float v3 = __half2float(hi.y) * ISC2;
            if (gc == d0)     { if (isNeg) v0 += 1.f; else g_diag[gi0] = v0; }
            if (gc + 1 == d0) { if (isNeg) v1 += 1.f; else g_diag[gi0] = v1; }
            if (gc == d1)     { if (isNeg) v2 += 1.f; else g_diag[gi1] = v2; }
            if (gc + 1 == d1) { if (isNeg) v3 += 1.f; else g_diag[gi1] = v3; }
            s0 += __expf(v0) + __expf(v1);
            s1 += __expf(v2) + __expf(v3);
        }
        s0 += __shfl_xor_sync(0xffffffffu, s0, 1);
        s0 += __shfl_xor_sync(0xffffffffu, s0, 2);
        s1 += __shfl_xor_sync(0xffffffffu, s1, 1);
        s1 += __shfl_xor_sync(0xffffffffu, s1, 2);
        if ((lane & 3) == 0) {
            sred[(wm * 64 + mt * 16 + g) * 4 + wn] = s0;
            sred[(wm * 64 + mt * 16 + g + 8) * 4 + wn] = s1;
        }
    }
    __syncthreads();
    if (tid < BM) {
        float s = sred[tid * 4] + sred[tid * 4 + 1] + sred[tid * 4 + 2] + sred[tid * 4 + 3];
        g_partial[(size_t)(rbase + tid) * CT_N + ct] = s;
    }
}

// ---------------------------------------------------------------------------
// Kernel 3a: per-row loss (1 thread/row, fully parallel)
// ---------------------------------------------------------------------------
__global__ void __launch_bounds__(256) rowloss_kernel() {
    const int row = blockIdx.x * 256 + threadIdx.x;
    const float4* p = (const float4*)&g_partial[(size_t)row * CT_N];
    float s = 0.f;
#pragma unroll
    for (int c = 0; c < CT_N / 4; c++) {
        float4 v = p[c];
        s += v.x + v.y + v.z + v.w;
    }
    g_rowloss[row] = logf(s) - g_diag[row];
}

// ---------------------------------------------------------------------------
// Kernel 3b: reduce row losses -> scalar mean
// ---------------------------------------------------------------------------
__global__ void __launch_bounds__(256) reduce_kernel(float* __restrict__ out) {
    __shared__ float sm[256];
    const int tid = threadIdx.x;
    const float4* p = (const float4*)g_rowloss;
    float local = 0.f;
#pragma unroll
    for (int i = 0; i < 4; i++) {
        float4 v = p[tid + i * 256];
        local += v.x + v.y + v.z + v.w;
    }
    sm[tid] = local;
    __syncthreads();
#pragma unroll
    for (int o = 128; o; o >>= 1) {
        if (tid < o) sm[tid] += sm[tid + o];
        __syncthreads();
    }
    if (tid == 0) out[0] = sm[0] * (1.0f / N_ROWS);
}

// ---------------------------------------------------------------------------
extern "C" void kernel_launch(void* const* d_in, const int* in_sizes, int n_in,
                              void* d_out, int out_size) {
    const float* x = (const float*)d_in[0];
    const float* t = (const float*)d_in[1];
    const float* h = (const float*)d_in[2];
    float* out = (float*)d_out;

    cudaFuncSetAttribute(sim_fp8_kernel,
                         cudaFuncAttributeMaxDynamicSharedMemorySize, SMEM_TOTAL);

    norm_convert_kernel<<<(3 * N_ROWS) / 8, 256>>>(x, t, h);

    dim3 grid(CT_N, RT_N);
    sim_fp8_kernel<<<grid, NTHREADS, SMEM_TOTAL>>>();

    rowloss_kernel<<<N_ROWS / 256, 256>>>();
    reduce_kernel<<<1, 256>>>(out);
}